// round 3
// baseline (speedup 1.0000x reference)
#include <cuda_runtime.h>
#include <math.h>
#include <stdint.h>

#define N_NODES 100000
#define N_EDGES 1600000
#define DIM 128

// ---------------- device scratch (no allocations allowed) ----------------
__device__ float g_agg[(size_t)N_NODES * DIM];   // aggregation buffer (reused both layers)
__device__ float g_h[(size_t)N_NODES * DIM];     // layer-1 output
__device__ int   g_count[N_NODES];
__device__ int   g_off[N_NODES + 1];
__device__ int   g_cursor[N_NODES];
__device__ int   g_ssrc[N_EDGES];                // src node ids sorted by dst

// ---------------- CSR build ----------------
__global__ void k_zero_counts() {
    int i = blockIdx.x * blockDim.x + threadIdx.x;
    if (i < N_NODES) g_count[i] = 0;
}

__global__ void k_hist(const int* __restrict__ dst) {
    int i = blockIdx.x * blockDim.x + threadIdx.x;
    if (i < N_EDGES) atomicAdd(&g_count[dst[i]], 1);
}

// single-block exclusive scan of g_count -> g_off (and g_cursor copy)
__global__ void k_scan() {
    __shared__ int ssum[1024];
    const int t = threadIdx.x;
    const int CH = (N_NODES + 1023) / 1024;   // 98
    int beg = t * CH;
    int end = beg + CH; if (end > N_NODES) end = N_NODES;
    int s = 0;
    for (int i = beg; i < end; i++) s += g_count[i];
    ssum[t] = s;
    __syncthreads();
    // Hillis-Steele inclusive scan
    for (int d = 1; d < 1024; d <<= 1) {
        int v = (t >= d) ? ssum[t - d] : 0;
        __syncthreads();
        ssum[t] += v;
        __syncthreads();
    }
    int run = (t == 0) ? 0 : ssum[t - 1];
    for (int i = beg; i < end; i++) {
        g_off[i] = run;
        g_cursor[i] = run;
        run += g_count[i];
    }
    if (t == 0) g_off[N_NODES] = N_EDGES;
}

__global__ void k_bin(const int* __restrict__ src, const int* __restrict__ dst) {
    int i = blockIdx.x * blockDim.x + threadIdx.x;
    if (i < N_EDGES) {
        int d = dst[i];
        int p = atomicAdd(&g_cursor[d], 1);
        g_ssrc[p] = src[i];
    }
}

// ---------------- segment max: one warp per destination node ----------------
__global__ void k_segmax(const float* __restrict__ feat, float* __restrict__ agg) {
    int gw = (blockIdx.x * blockDim.x + threadIdx.x) >> 5;
    if (gw >= N_NODES) return;
    const int lane = threadIdx.x & 31;
    const int beg = g_off[gw];
    const int end = g_off[gw + 1];
    const float NEG = __int_as_float(0xff800000);  // -inf
    float4 acc = make_float4(NEG, NEG, NEG, NEG);
    for (int e = beg; e < end; e++) {
        int s = g_ssrc[e];
        float4 v = *((const float4*)(feat + (size_t)s * DIM) + lane);
        acc.x = fmaxf(acc.x, v.x);
        acc.y = fmaxf(acc.y, v.y);
        acc.z = fmaxf(acc.z, v.z);
        acc.w = fmaxf(acc.w, v.w);
    }
    if (beg == end) acc = make_float4(0.f, 0.f, 0.f, 0.f);   // PyG: no-edge nodes -> 0
    *((float4*)(agg + (size_t)gw * DIM) + lane) = acc;
}

// ---------------- fused linear: out = L2norm(agg@Wl + x@Wr + b) [+relu] ----------------
// GEMM view: C[32 x D_OUT] = A[32 x 256] * W[256 x D_OUT], A = [agg | x], W = [Wl ; Wr]
template <int D_OUT, bool RELU>
__global__ void k_linear(const float* __restrict__ agg,
                         const float* __restrict__ xin,
                         const float* __restrict__ Wl,
                         const float* __restrict__ Wr,
                         const float* __restrict__ bias,
                         float* __restrict__ out) {
    constexpr int TILE = 32;          // nodes per block
    constexpr int K    = 128;
    constexpr int K2   = 256;
    constexpr int PAD  = TILE + 4;    // 36 floats: keeps 16B alignment, avoids conflicts
    constexpr int TC   = 8;           // cols per thread
    constexpr int CT   = D_OUT / TC;  // col-thread count (16 or 8)
    constexpr int RT   = 128 / CT;    // row-thread count (8 or 16)
    constexpr int TR   = TILE / RT;   // rows per thread (4 or 2)

    extern __shared__ float smem[];
    float* sW  = smem;                 // [K2][D_OUT]
    float* sA  = sW + K2 * D_OUT;      // [K2][PAD]  (k-major, transposed A)
    float* sSq = sA + K2 * PAD;        // [TILE]

    const int tid = threadIdx.x;
    const int node0 = blockIdx.x * TILE;

    // stage weights: Wl -> k in [0,128), Wr -> k in [128,256)
    for (int i = tid; i < K * D_OUT / 4; i += 128) {
        ((float4*)sW)[i] = ((const float4*)Wl)[i];
        ((float4*)(sW + K * D_OUT))[i] = ((const float4*)Wr)[i];
    }
    // stage A transposed into smem
    for (int i = tid; i < TILE * (K / 4); i += 128) {
        int r  = i / (K / 4);
        int k4 = (i % (K / 4)) * 4;
        float4 va = *(const float4*)(agg + (size_t)(node0 + r) * K + k4);
        float4 vx = *(const float4*)(xin + (size_t)(node0 + r) * K + k4);
        sA[(k4 + 0) * PAD + r] = va.x;
        sA[(k4 + 1) * PAD + r] = va.y;
        sA[(k4 + 2) * PAD + r] = va.z;
        sA[(k4 + 3) * PAD + r] = va.w;
        sA[(K + k4 + 0) * PAD + r] = vx.x;
        sA[(K + k4 + 1) * PAD + r] = vx.y;
        sA[(K + k4 + 2) * PAD + r] = vx.z;
        sA[(K + k4 + 3) * PAD + r] = vx.w;
    }
    if (tid < TILE) sSq[tid] = 0.f;
    __syncthreads();

    const int tc = tid % CT, tr = tid / CT;
    const int col0 = tc * TC, row0 = tr * TR;

    float acc[TR][TC];
#pragma unroll
    for (int r = 0; r < TR; r++)
#pragma unroll
        for (int c = 0; c < TC; c++) acc[r][c] = 0.f;

#pragma unroll 8
    for (int k = 0; k < K2; k++) {
        float a[TR];
#pragma unroll
        for (int r = 0; r < TR; r++) a[r] = sA[k * PAD + row0 + r];
        float4 w0 = *(const float4*)(sW + k * D_OUT + col0);
        float4 w1 = *(const float4*)(sW + k * D_OUT + col0 + 4);
        float w[TC] = {w0.x, w0.y, w0.z, w0.w, w1.x, w1.y, w1.z, w1.w};
#pragma unroll
        for (int r = 0; r < TR; r++)
#pragma unroll
            for (int c = 0; c < TC; c++)
                acc[r][c] = fmaf(a[r], w[c], acc[r][c]);
    }

    // bias + per-row sum of squares
    float bv[TC];
#pragma unroll
    for (int c = 0; c < TC; c++) bv[c] = bias[col0 + c];
#pragma unroll
    for (int r = 0; r < TR; r++) {
        float s = 0.f;
#pragma unroll
        for (int c = 0; c < TC; c++) {
            acc[r][c] += bv[c];
            s = fmaf(acc[r][c], acc[r][c], s);
        }
        atomicAdd(&sSq[row0 + r], s);
    }
    __syncthreads();

#pragma unroll
    for (int r = 0; r < TR; r++) {
        float inv = 1.f / fmaxf(sqrtf(sSq[row0 + r]), 1e-12f);
        float v[TC];
#pragma unroll
        for (int c = 0; c < TC; c++) {
            float o = acc[r][c] * inv;
            if (RELU) o = fmaxf(o, 0.f);
            v[c] = o;
        }
        float* op = out + (size_t)(node0 + row0 + r) * D_OUT + col0;
        *(float4*)(op)     = make_float4(v[0], v[1], v[2], v[3]);
        *(float4*)(op + 4) = make_float4(v[4], v[5], v[6], v[7]);
    }
}

// ---------------- host ----------------
extern "C" void kernel_launch(void* const* d_in, const int* in_sizes, int n_in,
                              void* d_out, int out_size) {
    const float* x   = (const float*)d_in[0];
    const int*   ei  = (const int*)d_in[1];
    const float* Wl1 = (const float*)d_in[2];
    const float* Wr1 = (const float*)d_in[3];
    const float* b1  = (const float*)d_in[4];
    const float* Wl2 = (const float*)d_in[5];
    const float* Wr2 = (const float*)d_in[6];
    const float* b2  = (const float*)d_in[7];
    float* out = (float*)d_out;

    const int* src = ei;             // edge_index[0]
    const int* dst = ei + N_EDGES;   // edge_index[1]

    float *agg, *h;
    cudaGetSymbolAddress((void**)&agg, g_agg);
    cudaGetSymbolAddress((void**)&h, g_h);

    const int SMEM1 = (256 * 128 + 256 * 36 + 32) * 4;  // 168064 B
    const int SMEM2 = (256 * 64  + 256 * 36 + 32) * 4;  // 102528 B
    cudaFuncSetAttribute(k_linear<128, true>,  cudaFuncAttributeMaxDynamicSharedMemorySize, SMEM1);
    cudaFuncSetAttribute(k_linear<64, false>,  cudaFuncAttributeMaxDynamicSharedMemorySize, SMEM2);

    // CSR build (edge_index is an input, so rebuilt every run; deterministic output
    // since max-aggregation is order-invariant)
    k_zero_counts<<<(N_NODES + 255) / 256, 256>>>();
    k_hist<<<(N_EDGES + 255) / 256, 256>>>(dst);
    k_scan<<<1, 1024>>>();
    k_bin<<<(N_EDGES + 255) / 256, 256>>>(src, dst);

    const int segmax_blocks = (N_NODES * 32 + 255) / 256;

    // layer 1
    k_segmax<<<segmax_blocks, 256>>>(x, agg);
    k_linear<128, true><<<N_NODES / 32, 128, SMEM1>>>(agg, x, Wl1, Wr1, b1, h);

    // layer 2
    k_segmax<<<segmax_blocks, 256>>>(h, agg);
    k_linear<64, false><<<N_NODES / 32, 128, SMEM2>>>(agg, h, Wl2, Wr2, b2, out);
}

// round 5
// speedup vs baseline: 2.7065x; 2.7065x over previous
#include <cuda_runtime.h>
#include <math.h>
#include <stdint.h>

#define N_NODES 100000
#define N_EDGES 1600000
#define DIM 128

typedef unsigned long long ull;

// ---------------- device scratch (no allocations allowed) ----------------
__device__ float g_agg[(size_t)N_NODES * DIM];
__device__ float g_h[(size_t)N_NODES * DIM];
__device__ int   g_count[N_NODES];
__device__ int   g_off[N_NODES + 1];
__device__ int   g_cursor[N_NODES];
__device__ int   g_ssrc[N_EDGES];

// ---------------- packed fp32x2 helpers (Blackwell FFMA2) ----------------
__device__ __forceinline__ ull dup2(float x) {
    unsigned int u = __float_as_uint(x);
    return ((ull)u << 32) | (ull)u;
}
__device__ __forceinline__ void ffma2(ull& d, ull a, ull b) {
    asm("fma.rn.f32x2 %0, %1, %2, %3;" : "=l"(d) : "l"(a), "l"(b), "l"(d));
}
__device__ __forceinline__ float lo32(ull v) { return __uint_as_float((unsigned int)v); }
__device__ __forceinline__ float hi32(ull v) { return __uint_as_float((unsigned int)(v >> 32)); }

// ---------------- CSR build ----------------
__global__ void k_hist(const int* __restrict__ dst) {
    int i = blockIdx.x * blockDim.x + threadIdx.x;
    if (i < N_EDGES) atomicAdd(&g_count[dst[i]], 1);
}

// single-block exclusive scan of g_count -> g_off (and g_cursor copy)
__global__ void k_scan() {
    __shared__ int ssum[1024];
    const int t = threadIdx.x;
    const int CH = (N_NODES + 1023) / 1024;   // 98
    int beg = t * CH;
    int end = beg + CH; if (end > N_NODES) end = N_NODES;
    int s = 0;
    for (int i = beg; i < end; i++) s += g_count[i];
    ssum[t] = s;
    __syncthreads();
    for (int d = 1; d < 1024; d <<= 1) {
        int v = (t >= d) ? ssum[t - d] : 0;
        __syncthreads();
        ssum[t] += v;
        __syncthreads();
    }
    int run = (t == 0) ? 0 : ssum[t - 1];
    for (int i = beg; i < end; i++) {
        g_off[i] = run;
        g_cursor[i] = run;
        run += g_count[i];
    }
    if (t == 0) g_off[N_NODES] = N_EDGES;
}

__global__ void k_bin(const int* __restrict__ src, const int* __restrict__ dst) {
    int i = blockIdx.x * blockDim.x + threadIdx.x;
    if (i < N_EDGES) {
        int d = dst[i];
        int p = atomicAdd(&g_cursor[d], 1);
        g_ssrc[p] = src[i];
    }
}

// ---------------- segment max: one warp per node, MLP-4 unrolled ----------------
__global__ void k_segmax(const float* __restrict__ feat, float* __restrict__ agg) {
    int gw = (blockIdx.x * blockDim.x + threadIdx.x) >> 5;
    if (gw >= N_NODES) return;
    const int lane = threadIdx.x & 31;
    const int beg = __ldg(&g_off[gw]);
    const int end = __ldg(&g_off[gw + 1]);
    const float NEG = __int_as_float(0xff800000);  // -inf
    float4 acc = make_float4(NEG, NEG, NEG, NEG);
    int e = beg;
    for (; e + 4 <= end; e += 4) {
        int s0 = __ldg(&g_ssrc[e]);
        int s1 = __ldg(&g_ssrc[e + 1]);
        int s2 = __ldg(&g_ssrc[e + 2]);
        int s3 = __ldg(&g_ssrc[e + 3]);
        float4 v0 = __ldg((const float4*)(feat + (size_t)s0 * DIM) + lane);
        float4 v1 = __ldg((const float4*)(feat + (size_t)s1 * DIM) + lane);
        float4 v2 = __ldg((const float4*)(feat + (size_t)s2 * DIM) + lane);
        float4 v3 = __ldg((const float4*)(feat + (size_t)s3 * DIM) + lane);
        acc.x = fmaxf(fmaxf(fmaxf(acc.x, v0.x), fmaxf(v1.x, v2.x)), v3.x);
        acc.y = fmaxf(fmaxf(fmaxf(acc.y, v0.y), fmaxf(v1.y, v2.y)), v3.y);
        acc.z = fmaxf(fmaxf(fmaxf(acc.z, v0.z), fmaxf(v1.z, v2.z)), v3.z);
        acc.w = fmaxf(fmaxf(fmaxf(acc.w, v0.w), fmaxf(v1.w, v2.w)), v3.w);
    }
    for (; e < end; e++) {
        int s = __ldg(&g_ssrc[e]);
        float4 v = __ldg((const float4*)(feat + (size_t)s * DIM) + lane);
        acc.x = fmaxf(acc.x, v.x);
        acc.y = fmaxf(acc.y, v.y);
        acc.z = fmaxf(acc.z, v.z);
        acc.w = fmaxf(acc.w, v.w);
    }
    if (beg == end) acc = make_float4(0.f, 0.f, 0.f, 0.f);
    *((float4*)(agg + (size_t)gw * DIM) + lane) = acc;
}

// ---------------- fused GEMM: out = L2norm(agg@Wl + x@Wr + b) [+relu] ----------------
// C[128 x DN] = A[128 x 256] * W[256 x DN], A = [agg | x], W = [Wl ; Wr]
// 256 threads, thread tile 8 rows x TC cols; rows packed as fp32x2 pairs (FFMA2).
template <int DN, bool RELU>
__global__ void __launch_bounds__(256, 2)
k_gemm(const float* __restrict__ agg, const float* __restrict__ xin,
       const float* __restrict__ Wl, const float* __restrict__ Wr,
       const float* __restrict__ bias, float* __restrict__ out) {
    constexpr int KC  = 32;
    constexpr int AST = 132;          // sA row stride (floats), 16B-aligned, pad vs conflicts
    constexpr int TC  = DN / 16;      // 8 (DN=128) or 4 (DN=64) cols per thread

    __shared__ float sA[KC * AST];    // [k][m]
    __shared__ float sB[KC * DN];     // [k][n]

    const int tid   = threadIdx.x;
    const int node0 = blockIdx.x * 128;
    const int tc    = tid & 15;       // 16 col-threads
    const int tr    = tid >> 4;       // 16 row-threads
    const int row0  = tr * 8;
    const int col0  = tc * TC;

    ull acc[4][TC];
#pragma unroll
    for (int rp = 0; rp < 4; rp++)
#pragma unroll
        for (int c = 0; c < TC; c++) acc[rp][c] = 0ull;

    // A loader mapping: 2 threads per row, 16 floats each
    const int lr = tid >> 1;
    const int lk = (tid & 1) * 16;
    const size_t lrow = (size_t)min(node0 + lr, N_NODES - 1);

    for (int kb = 0; kb < 256; kb += KC) {
        const float* abase = (kb < 128) ? agg : xin;
        const float* wbase = (kb < 128) ? Wl : Wr;
        const int ko = kb & 127;

        // stage A chunk transposed: sA[k][m]
        {
            const float* ap = abase + lrow * DIM + ko + lk;
            float4 v[4];
#pragma unroll
            for (int j = 0; j < 4; j++) v[j] = *(const float4*)(ap + j * 4);
#pragma unroll
            for (int j = 0; j < 4; j++) {
                sA[(lk + j * 4 + 0) * AST + lr] = v[j].x;
                sA[(lk + j * 4 + 1) * AST + lr] = v[j].y;
                sA[(lk + j * 4 + 2) * AST + lr] = v[j].z;
                sA[(lk + j * 4 + 3) * AST + lr] = v[j].w;
            }
        }
        // stage W chunk (already k-major, direct copy)
        {
            const float4* wp = (const float4*)(wbase + (size_t)ko * DN);
            for (int i = tid; i < KC * DN / 4; i += 256)
                ((float4*)sB)[i] = wp[i];
        }
        __syncthreads();

#pragma unroll 8
        for (int k = 0; k < KC; k++) {
            // 8 A rows as 4 packed fp32x2 pairs (m-contiguous in sA -> free packing)
            ulonglong2 a01 = *(const ulonglong2*)&sA[k * AST + row0];
            ulonglong2 a23 = *(const ulonglong2*)&sA[k * AST + row0 + 4];
            ull ap_[4] = {a01.x, a01.y, a23.x, a23.y};
            // W values, duplicated into both halves (alu pipe, overlaps fma)
            float wreg[TC];
            float4 w0 = *(const float4*)&sB[k * DN + col0];
            wreg[0] = w0.x; wreg[1] = w0.y; wreg[2] = w0.z; wreg[3] = w0.w;
            if (TC == 8) {
                float4 w1 = *(const float4*)&sB[k * DN + col0 + 4];
                wreg[4] = w1.x; wreg[5] = w1.y; wreg[6] = w1.z; wreg[7] = w1.w;
            }
            ull wd[TC];
#pragma unroll
            for (int c = 0; c < TC; c++) wd[c] = dup2(wreg[c]);
#pragma unroll
            for (int rp = 0; rp < 4; rp++)
#pragma unroll
                for (int c = 0; c < TC; c++) ffma2(acc[rp][c], ap_[rp], wd[c]);
        }
        __syncthreads();
    }

    // ---- epilogue: bias, row L2-norm (shfl over the 16-thread row group), relu, store
    float bv[TC];
#pragma unroll
    for (int c = 0; c < TC; c++) bv[c] = __ldg(&bias[col0 + c]);

    float ssq[8];
#pragma unroll
    for (int r = 0; r < 8; r++) ssq[r] = 0.f;
#pragma unroll
    for (int rp = 0; rp < 4; rp++)
#pragma unroll
        for (int c = 0; c < TC; c++) {
            float e = lo32(acc[rp][c]) + bv[c];
            float o = hi32(acc[rp][c]) + bv[c];
            ssq[2 * rp]     = fmaf(e, e, ssq[2 * rp]);
            ssq[2 * rp + 1] = fmaf(o, o, ssq[2 * rp + 1]);
        }
    // reduce across the 16 threads sharing each row (lanes 0-15 / 16-31 groups)
#pragma unroll
    for (int d = 1; d < 16; d <<= 1)
#pragma unroll
        for (int r = 0; r < 8; r++)
            ssq[r] += __shfl_xor_sync(0xffffffffu, ssq[r], d);

    float inv[8];
#pragma unroll
    for (int r = 0; r < 8; r++)
        inv[r] = 1.f / fmaxf(sqrtf(ssq[r]), 1e-12f);

#pragma unroll
    for (int rp = 0; rp < 4; rp++) {
#pragma unroll
        for (int half = 0; half < 2; half++) {
            int r = 2 * rp + half;
            int node = node0 + row0 + r;
            if (node < N_NODES) {
                float v[TC];
#pragma unroll
                for (int c = 0; c < TC; c++) {
                    float f = (half ? hi32(acc[rp][c]) : lo32(acc[rp][c])) + bv[c];
                    f *= inv[r];
                    if (RELU) f = fmaxf(f, 0.f);
                    v[c] = f;
                }
                float* op = out + (size_t)node * DN + col0;
                *(float4*)op = make_float4(v[0], v[1], v[2], v[3]);
                if (TC == 8)
                    *(float4*)(op + 4) = make_float4(v[4], v[5], v[6], v[7]);
            }
        }
    }
}

// ---------------- host ----------------
extern "C" void kernel_launch(void* const* d_in, const int* in_sizes, int n_in,
                              void* d_out, int out_size) {
    const float* x   = (const float*)d_in[0];
    const int*   ei  = (const int*)d_in[1];
    const float* Wl1 = (const float*)d_in[2];
    const float* Wr1 = (const float*)d_in[3];
    const float* b1  = (const float*)d_in[4];
    const float* Wl2 = (const float*)d_in[5];
    const float* Wr2 = (const float*)d_in[6];
    const float* b2  = (const float*)d_in[7];
    float* out = (float*)d_out;

    const int* src = ei;
    const int* dst = ei + N_EDGES;

    float *agg, *h;
    int* cnt;
    cudaGetSymbolAddress((void**)&agg, g_agg);
    cudaGetSymbolAddress((void**)&h, g_h);
    cudaGetSymbolAddress((void**)&cnt, g_count);

    // CSR build (max-aggregation is order-invariant -> deterministic)
    cudaMemsetAsync(cnt, 0, N_NODES * sizeof(int));
    k_hist<<<(N_EDGES + 255) / 256, 256>>>(dst);
    k_scan<<<1, 1024>>>();
    k_bin<<<(N_EDGES + 255) / 256, 256>>>(src, dst);

    const int segmax_blocks = (N_NODES * 32 + 255) / 256;
    const int gemm_blocks = (N_NODES + 127) / 128;   // 782

    // layer 1
    k_segmax<<<segmax_blocks, 256>>>(x, agg);
    k_gemm<128, true><<<gemm_blocks, 256>>>(agg, x, Wl1, Wr1, b1, h);

    // layer 2
    k_segmax<<<segmax_blocks, 256>>>(h, agg);
    k_gemm<64, false><<<gemm_blocks, 256>>>(agg, h, Wl2, Wr2, b2, out);
}